// round 3
// baseline (speedup 1.0000x reference)
#include <cuda_runtime.h>

// TopoGroupDynamicMaskConv2d: B=2, CIN=192, COUT=384, H=W=48, K=5, P=2, G=2
// out[b, g*192+o, y, x] = dkb[b,g,o] +
//   sum_{c,kh,kw} dkw[b,g,o,c*25+kh*5+kw] * x[b,c,y+kh-2,x+kw-2]
//                 * [inbounds && topo[b, c/96, ys, xs] < topo[b, g, y, x]]

#define TW 53   // xs row stride (8 rows x 53)

__device__ __forceinline__ unsigned long long pack2(float v) {
    unsigned long long r;
    asm("mov.b64 %0, {%1, %1};" : "=l"(r) : "f"(v));
    return r;
}
__device__ __forceinline__ void ffma2(unsigned long long& d, unsigned long long a,
                                      unsigned long long b) {
    asm("fma.rn.f32x2 %0, %1, %2, %0;" : "+l"(d) : "l"(a), "l"(b));
}
__device__ __forceinline__ void unpack2(unsigned long long v, float& lo, float& hi) {
    asm("mov.b64 {%0, %1}, %2;" : "=f"(lo), "=f"(hi) : "l"(v));
}

__global__ __launch_bounds__(256)
void topo_conv_kernel(const float* __restrict__ xin,
                      const int*   __restrict__ topo,
                      const float* __restrict__ dkw,
                      const float* __restrict__ dkb,
                      float*       __restrict__ out)
{
    const int lt  = blockIdx.x;          // 0..11 : 4-row pixel tiles
    const int ot  = blockIdx.y;          // 0..2  : 64-channel output tiles
    const int bg  = blockIdx.z;          // 0..3  : (b,g)
    const int b   = bg >> 1, g = bg & 1;
    const int y0  = lt * 4;
    const int o0  = ot * 64;
    const int tid = threadIdx.x;
    const int to  = tid & 3;             // 0..3  -> o chunk of 16
    const int tl  = tid >> 2;            // 0..63 -> pixels tl, tl+64, tl+128

    __shared__ __align__(16) float xs[2][8 * TW];
    __shared__ __align__(16) float ws[2][25 * 64];
    __shared__ int topoS[2][8 * 52];

    // ---- stage topo patches for both channel groups (127 = OOB sentinel) ----
    const int* topo_b = topo + b * 2 * 2304;
    for (int idx = tid; idx < 2 * 8 * 52; idx += 256) {
        int gi  = idx / (8 * 52);
        int rem = idx - gi * (8 * 52);
        int r   = rem / 52;
        int cc  = rem - r * 52;
        int yy  = y0 + r - 2;
        int xx  = cc - 2;
        int v = 127;
        if (yy >= 0 && yy < 48 && xx >= 0 && xx < 48)
            v = topo_b[gi * 2304 + yy * 48 + xx];
        topoS[gi][r * 52 + cc] = v;
    }
    __syncthreads();

    // ---- per-thread pixel mapping + 25-bit causal masks (one per g_in) ----
    int lrow[3], lcol[3], xbase[3];
    unsigned mbA[3], mbB[3];             // g_in = 0 (c<96), g_in = 1 (c>=96)
    #pragma unroll
    for (int j = 0; j < 3; j++) {
        int l = tl + 64 * j;             // 0..191
        int r = l / 48;
        int ccol = l - r * 48;
        lrow[j] = r; lcol[j] = ccol;
        xbase[j] = r * TW + ccol;
        int tc = topoS[g][(r + 2) * 52 + ccol + 2];
        unsigned m0 = 0, m1 = 0;
        #pragma unroll
        for (int kh = 0; kh < 5; kh++)
            #pragma unroll
            for (int kw = 0; kw < 5; kw++) {
                int off = (r + kh) * 52 + ccol + kw;
                if (topoS[0][off] < tc) m0 |= 1u << (kh * 5 + kw);
                if (topoS[1][off] < tc) m1 |= 1u << (kh * 5 + kw);
            }
        mbA[j] = m0; mbB[j] = m1;
    }

    // ---- precompute gmem/smem load slots (fixed across the c loop) ----
    const float* xb = xin + b * 192 * 2304;
    const float* wb = dkw + (size_t)((b * 2 + g) * 192 + o0) * 4800;

    const float* wptr[7]; int wsoff[7]; bool wval[7];
    #pragma unroll
    for (int j = 0; j < 7; j++) {
        int idx = tid + j * 256;
        wval[j] = (idx < 1600);
        int o = idx / 25;
        int k = idx - o * 25;
        if (!wval[j]) { o = 0; k = 0; }
        wptr[j]  = wb + o * 4800 + k;
        wsoff[j] = k * 64 + o;           // smem layout: ws[kidx*64 + o]
    }

    const float* xptr[2]; int xsoff[2]; bool xinb[2], xact[2];
    #pragma unroll
    for (int j = 0; j < 2; j++) {
        int idx = tid + j * 256;
        bool act = (idx < 416);          // 8*52 patch entries
        int r  = idx / 52;
        int cc = idx - r * 52;
        int yy = y0 + r - 2;
        int xx = cc - 2;
        bool inb = act && yy >= 0 && yy < 48 && xx >= 0 && xx < 48;
        xact[j] = act;
        xinb[j] = inb;
        xptr[j] = xb + (inb ? (yy * 48 + xx) : 0);
        xsoff[j] = act ? (r * TW + cc) : 0;
    }

    // ---- accumulators: 8 f32x2 pairs (16 output channels) x 3 pixels ----
    unsigned long long acc[8][3];
    #pragma unroll
    for (int p = 0; p < 8; p++)
        #pragma unroll
        for (int j = 0; j < 3; j++) acc[p][j] = 0ull;

    // ---- prime buffer 0 with channel 0 ----
    float pw[7], px[2];
    #pragma unroll
    for (int j = 0; j < 7; j++) pw[j] = wval[j] ? wptr[j][0] : 0.f;
    #pragma unroll
    for (int j = 0; j < 2; j++) px[j] = xinb[j] ? xptr[j][0] : 0.f;
    #pragma unroll
    for (int j = 0; j < 7; j++) if (wval[j]) ws[0][wsoff[j]] = pw[j];
    #pragma unroll
    for (int j = 0; j < 2; j++) if (xact[j]) xs[0][xsoff[j]] = px[j];
    __syncthreads();

    // ---- main loop over 192 input channels, double-buffered ----
    for (int c = 0; c < 192; c++) {
        const int buf = c & 1;
        const int cn  = c + 1;

        // prefetch next channel into registers (overlaps with compute)
        if (cn < 192) {
            #pragma unroll
            for (int j = 0; j < 7; j++) pw[j] = wval[j] ? wptr[j][cn * 25] : 0.f;
            #pragma unroll
            for (int j = 0; j < 2; j++) px[j] = xinb[j] ? xptr[j][cn * 2304] : 0.f;
        }

        const unsigned M0 = (c < 96) ? mbA[0] : mbB[0];
        const unsigned M1 = (c < 96) ? mbA[1] : mbB[1];
        const unsigned M2 = (c < 96) ? mbA[2] : mbB[2];

        const float* wrow = &ws[buf][to * 16];
        const float* xrow = &xs[buf][0];

        #pragma unroll
        for (int kidx = 0; kidx < 25; kidx++) {
            const int koff = (kidx / 5) * TW + (kidx % 5);

            ulonglong2 wv0 = *(const ulonglong2*)(wrow + kidx * 64);
            ulonglong2 wv1 = *(const ulonglong2*)(wrow + kidx * 64 + 4);
            ulonglong2 wv2 = *(const ulonglong2*)(wrow + kidx * 64 + 8);
            ulonglong2 wv3 = *(const ulonglong2*)(wrow + kidx * 64 + 12);

            float x0 = xrow[xbase[0] + koff];
            float x1 = xrow[xbase[1] + koff];
            float x2 = xrow[xbase[2] + koff];
            x0 = ((M0 >> kidx) & 1u) ? x0 : 0.f;
            x1 = ((M1 >> kidx) & 1u) ? x1 : 0.f;
            x2 = ((M2 >> kidx) & 1u) ? x2 : 0.f;
            unsigned long long xp0 = pack2(x0);
            unsigned long long xp1 = pack2(x1);
            unsigned long long xp2 = pack2(x2);

            ffma2(acc[0][0], wv0.x, xp0); ffma2(acc[0][1], wv0.x, xp1); ffma2(acc[0][2], wv0.x, xp2);
            ffma2(acc[1][0], wv0.y, xp0); ffma2(acc[1][1], wv0.y, xp1); ffma2(acc[1][2], wv0.y, xp2);
            ffma2(acc[2][0], wv1.x, xp0); ffma2(acc[2][1], wv1.x, xp1); ffma2(acc[2][2], wv1.x, xp2);
            ffma2(acc[3][0], wv1.y, xp0); ffma2(acc[3][1], wv1.y, xp1); ffma2(acc[3][2], wv1.y, xp2);
            ffma2(acc[4][0], wv2.x, xp0); ffma2(acc[4][1], wv2.x, xp1); ffma2(acc[4][2], wv2.x, xp2);
            ffma2(acc[5][0], wv2.y, xp0); ffma2(acc[5][1], wv2.y, xp1); ffma2(acc[5][2], wv2.y, xp2);
            ffma2(acc[6][0], wv3.x, xp0); ffma2(acc[6][1], wv3.x, xp1); ffma2(acc[6][2], wv3.x, xp2);
            ffma2(acc[7][0], wv3.y, xp0); ffma2(acc[7][1], wv3.y, xp1); ffma2(acc[7][2], wv3.y, xp2);
        }

        __syncthreads();
        if (cn < 192) {
            const int nb = cn & 1;
            #pragma unroll
            for (int j = 0; j < 7; j++) if (wval[j]) ws[nb][wsoff[j]] = pw[j];
            #pragma unroll
            for (int j = 0; j < 2; j++) if (xact[j]) xs[nb][xsoff[j]] = px[j];
        }
        __syncthreads();
    }

    // ---- epilogue: bias + store ----
    const float* bb = dkb + ((b * 2 + g) * 192 + o0 + to * 16);
    float* ob = out + ((size_t)((b * 2 + g) * 192 + o0 + to * 16)) * 2304 + y0 * 48;

    #pragma unroll
    for (int p = 0; p < 8; p++) {
        float b0 = bb[2 * p];
        float b1 = bb[2 * p + 1];
        #pragma unroll
        for (int j = 0; j < 3; j++) {
            float lo, hi;
            unpack2(acc[p][j], lo, hi);
            int pix = lrow[j] * 48 + lcol[j];
            ob[(size_t)(2 * p) * 2304 + pix]     = lo + b0;
            ob[(size_t)(2 * p + 1) * 2304 + pix] = hi + b1;
        }
    }
}

extern "C" void kernel_launch(void* const* d_in, const int* in_sizes, int n_in,
                              void* d_out, int out_size) {
    const float* x    = (const float*)d_in[0];   // (2,192,48,48) f32
    const int*   topo = (const int*)  d_in[1];   // (2,2,48,48)  i32
    const float* dkw  = (const float*)d_in[2];   // (2,2,192,4800,1) f32
    const float* dkb  = (const float*)d_in[3];   // (2,2,192,1) f32
    float* out = (float*)d_out;                  // (2,384,48,48) f32

    dim3 grid(12, 3, 4);                         // 144 blocks = 1 wave
    topo_conv_kernel<<<grid, 256>>>(x, topo, dkw, dkb, out);
}

// round 4
// speedup vs baseline: 1.6075x; 1.6075x over previous
#include <cuda_runtime.h>

// TopoGroupDynamicMaskConv2d: B=2, CIN=192, COUT=384, H=W=48, K=5, P=2, G=2
// K-split over input channels (kz=0: c<96 / g_in=0, kz=1: c>=96 / g_in=1),
// combined via atomicAdd into a zero-initialized output.

#define TW 54   // xs row stride in floats (8 rows x 54, 8B-aligned rows)

__device__ __forceinline__ unsigned long long pack2(float v) {
    unsigned long long r;
    asm("mov.b64 %0, {%1, %1};" : "=l"(r) : "f"(v));
    return r;
}
__device__ __forceinline__ void ffma2(unsigned long long& d, unsigned long long a,
                                      unsigned long long b) {
    asm("fma.rn.f32x2 %0, %1, %2, %0;" : "+l"(d) : "l"(a), "l"(b));
}
__device__ __forceinline__ void unpack2(unsigned long long v, float& lo, float& hi) {
    asm("mov.b64 {%0, %1}, %2;" : "=f"(lo), "=f"(hi) : "l"(v));
}

__global__ void zero_out_kernel(float4* out, int n4) {
    int i = blockIdx.x * blockDim.x + threadIdx.x;
    if (i < n4) out[i] = make_float4(0.f, 0.f, 0.f, 0.f);
}

__global__ __launch_bounds__(256, 2)
void topo_conv_kernel(const float* __restrict__ xin,
                      const int*   __restrict__ topo,
                      const float* __restrict__ dkw,
                      const float* __restrict__ dkb,
                      float*       __restrict__ out)
{
    const int lt  = blockIdx.x;          // 0..11 : 4-row pixel tiles
    const int ot  = blockIdx.y;          // 0..2  : 64-channel output tiles
    const int zz  = blockIdx.z;          // 0..7  : (b,g) x kz
    const int bg  = zz & 3;
    const int kz  = zz >> 2;             // channel half; g_in == kz
    const int b   = bg >> 1, g = bg & 1;
    const int y0  = lt * 4;
    const int o0  = ot * 64;
    const int c0  = kz * 96;
    const int tid = threadIdx.x;
    const int og  = tid & 7;             // 0..7 -> 8 output channels og*8..og*8+7
    const int pg  = tid >> 3;            // 0..31
    const int r   = pg >> 3;             // local row 0..3
    const int pc  = (pg & 7) * 6;        // col base: 6 consecutive pixels

    __shared__ __align__(16) float xs[2][8 * TW];
    __shared__ __align__(16) float ws[2][25 * 64];
    __shared__ int topoS[2][8 * 52];

    // ---- stage topo patches (127 = OOB sentinel; pad never passes '<') ----
    const int* topo_b = topo + b * 2 * 2304;
    for (int idx = tid; idx < 2 * 8 * 52; idx += 256) {
        int gi  = idx / (8 * 52);
        int rem = idx - gi * (8 * 52);
        int rr  = rem / 52;
        int cc  = rem - rr * 52;
        int yy  = y0 + rr - 2;
        int xx  = cc - 2;
        int v = 127;
        if (yy >= 0 && yy < 48 && xx >= 0 && xx < 48)
            v = topo_b[gi * 2304 + yy * 48 + xx];
        topoS[gi][rr * 52 + cc] = v;
    }
    __syncthreads();

    // ---- 25-bit causal masks for 6 pixels (g_in = kz fixed for this CTA) ----
    unsigned mk[6];
    #pragma unroll
    for (int i = 0; i < 6; i++) {
        int tc = topoS[g][(r + 2) * 52 + pc + i + 2];
        unsigned m = 0;
        #pragma unroll
        for (int kh = 0; kh < 5; kh++)
            #pragma unroll
            for (int kw = 0; kw < 5; kw++)
                if (topoS[kz][(r + kh) * 52 + pc + i + kw] < tc)
                    m |= 1u << (kh * 5 + kw);
        mk[i] = m;
    }

    // ---- staging slots (fixed across channel loop) ----
    const float* xb = xin + (size_t)(b * 192 + c0) * 2304;
    const float* wb = dkw + (size_t)((b * 2 + g) * 192 + o0) * 4800 + c0 * 25;

    int woff[7], wsoff[7]; bool wval[7];
    #pragma unroll
    for (int j = 0; j < 7; j++) {
        int idx = tid + j * 256;
        wval[j] = (idx < 1600);
        int o = idx / 25;
        int k = idx - o * 25;
        if (!wval[j]) { o = 0; k = 0; }
        woff[j]  = o * 4800 + k;
        wsoff[j] = k * 64 + o;
    }

    int gxoff[2], xsoff[2]; bool xinb[2], xact[2];
    #pragma unroll
    for (int j = 0; j < 2; j++) {
        int idx = tid + j * 256;
        bool act = (idx < 416);          // 8*52 patch entries
        int rr = idx / 52;
        int cc = idx - rr * 52;
        int yy = y0 + rr - 2;
        int xx = cc - 2;
        bool inb = act && yy >= 0 && yy < 48 && xx >= 0 && xx < 48;
        xact[j]  = act;
        xinb[j]  = inb;
        gxoff[j] = inb ? (yy * 48 + xx) : 0;
        xsoff[j] = act ? (rr * TW + cc) : 0;
    }

    // ---- accumulators: 4 o-pairs x 6 pixels ----
    unsigned long long acc[4][6];
    #pragma unroll
    for (int p = 0; p < 4; p++)
        #pragma unroll
        for (int i = 0; i < 6; i++) acc[p][i] = 0ull;

    // ---- prime buffer 0 with channel 0 ----
    float pw[7], px[2];
    #pragma unroll
    for (int j = 0; j < 7; j++) pw[j] = wval[j] ? wb[woff[j]] : 0.f;
    #pragma unroll
    for (int j = 0; j < 2; j++) px[j] = xinb[j] ? xb[gxoff[j]] : 0.f;
    #pragma unroll
    for (int j = 0; j < 7; j++) if (wval[j]) ws[0][wsoff[j]] = pw[j];
    #pragma unroll
    for (int j = 0; j < 2; j++) if (xact[j]) xs[0][xsoff[j]] = px[j];
    __syncthreads();

    // ---- 96 channels, double-buffered ----
    for (int c = 0; c < 96; c++) {
        const int buf = c & 1;
        const int cn  = c + 1;

        if (cn < 96) {
            #pragma unroll
            for (int j = 0; j < 7; j++) pw[j] = wval[j] ? wb[woff[j] + cn * 25] : 0.f;
            #pragma unroll
            for (int j = 0; j < 2; j++) px[j] = xinb[j] ? xb[gxoff[j] + cn * 2304] : 0.f;
        }

        const float* wsb = &ws[buf][og * 8];
        const float* xpatch = &xs[buf][0];

        #pragma unroll
        for (int kh = 0; kh < 5; kh++) {
            // row cache: 10 values serve 6 pixels x 5 kw taps
            float xr[10];
            const float* xsr = xpatch + (r + kh) * TW + pc;
            #pragma unroll
            for (int t = 0; t < 5; t++) {
                float2 q = *(const float2*)(xsr + 2 * t);
                xr[2 * t] = q.x; xr[2 * t + 1] = q.y;
            }
            #pragma unroll
            for (int kw = 0; kw < 5; kw++) {
                const int kidx = kh * 5 + kw;
                ulonglong2 wva = *(const ulonglong2*)(wsb + kidx * 64);
                ulonglong2 wvb = *(const ulonglong2*)(wsb + kidx * 64 + 4);

                unsigned long long xp[6];
                #pragma unroll
                for (int i = 0; i < 6; i++) {
                    float f = ((mk[i] >> kidx) & 1u) ? xr[i + kw] : 0.f;
                    xp[i] = pack2(f);
                }
                #pragma unroll
                for (int i = 0; i < 6; i++) {
                    ffma2(acc[0][i], wva.x, xp[i]);
                    ffma2(acc[1][i], wva.y, xp[i]);
                    ffma2(acc[2][i], wvb.x, xp[i]);
                    ffma2(acc[3][i], wvb.y, xp[i]);
                }
            }
        }

        __syncthreads();
        if (cn < 96) {
            const int nb = cn & 1;
            #pragma unroll
            for (int j = 0; j < 7; j++) if (wval[j]) ws[nb][wsoff[j]] = pw[j];
            #pragma unroll
            for (int j = 0; j < 2; j++) if (xact[j]) xs[nb][xsoff[j]] = px[j];
        }
        __syncthreads();
    }

    // ---- epilogue: (bias from kz=0 only) + atomic accumulate ----
    const float* bb = dkb + ((b * 2 + g) * 192 + o0 + og * 8);
    float* ob = out + (size_t)(b * 384 + g * 192 + o0 + og * 8) * 2304
                    + (y0 + r) * 48 + pc;

    #pragma unroll
    for (int p = 0; p < 4; p++) {
        float b0 = (kz == 0) ? bb[2 * p]     : 0.f;
        float b1 = (kz == 0) ? bb[2 * p + 1] : 0.f;
        #pragma unroll
        for (int i = 0; i < 6; i++) {
            float lo, hi;
            unpack2(acc[p][i], lo, hi);
            atomicAdd(&ob[(size_t)(2 * p) * 2304 + i],     lo + b0);
            atomicAdd(&ob[(size_t)(2 * p + 1) * 2304 + i], hi + b1);
        }
    }
}

extern "C" void kernel_launch(void* const* d_in, const int* in_sizes, int n_in,
                              void* d_out, int out_size) {
    const float* x    = (const float*)d_in[0];   // (2,192,48,48) f32
    const int*   topo = (const int*)  d_in[1];   // (2,2,48,48)  i32
    const float* dkw  = (const float*)d_in[2];   // (2,2,192,4800,1) f32
    const float* dkb  = (const float*)d_in[3];   // (2,2,192,1) f32
    float* out = (float*)d_out;                  // (2,384,48,48) f32

    const int n4 = (2 * 384 * 2304) / 4;         // 442368 float4
    zero_out_kernel<<<(n4 + 255) / 256, 256>>>((float4*)out, n4);

    dim3 grid(12, 3, 8);                         // 288 blocks -> 2 CTAs/SM
    topo_conv_kernel<<<grid, 256>>>(x, topo, dkw, dkb, out);
}

// round 7
// speedup vs baseline: 3.4697x; 2.1585x over previous
#include <cuda_runtime.h>
#include <cuda_fp16.h>
#include <cstdint>

// TopoGroupDynamicMaskConv2d via mma.sync m16n8k16 fp16 hi/lo (3-pass) GEMM.
// B=2, CIN=192, COUT=384, H=W=48, K=5, P=2, G=2.
// Per (b,g): D[2304px,192o] = Xm(masked im2col, K=192ch*32pad) * W^T, fp32 acc.
// 144 CTAs: 36 px-tiles(64) x 4 (b,g). No tcgen05 (harness targets plain sm_103).

#define NCHUNK 96            // chunks of K'=64 (2 channels x 32 padded taps)

// W in fragment-ready order: [bg][chunk][var(hi/lo)][nt 24][kt 4][lane 32][reg 2] b32
__device__ __align__(16) uint32_t g_wF[4u * 96u * 12288u];

// ---- dynamic smem layout (bytes) ----
#define OFF_A      0         // 2 buf x 2 var x 4 mt x 4 kt x 4 reg x 32 lane x 4B = 32768
#define OFF_B      32768     // 2 buf x 2 var x 24 nt x 4 kt x 32 lane x 2 reg x 4B = 98304
#define OFF_PATCH  131072    // 768 f32 (624 used: 2ch x 6 x 52)
#define OFF_TOPO   134144    // 624 ints (2 gi x 6 x 52)
#define OFF_MASK   136640    // 128 ints (2 gi x 64 px)
#define SMEM_TOTAL 137152

__device__ __forceinline__ uint32_t smem_u32(const void* p) {
    uint32_t a;
    asm("{ .reg .u64 t; cvta.to.shared.u64 t, %1; cvt.u32.u64 %0, t; }" : "=r"(a) : "l"(p));
    return a;
}
__device__ __forceinline__ uint32_t pack_h2(__half lo, __half hi) {
    return ((uint32_t)__half_as_ushort(hi) << 16) | (uint32_t)__half_as_ushort(lo);
}
__device__ __forceinline__ uint32_t lds32(uint32_t a) {
    uint32_t v; asm volatile("ld.shared.b32 %0,[%1];" : "=r"(v) : "r"(a)); return v;
}
__device__ __forceinline__ void lds64(uint32_t* v, uint32_t a) {
    asm volatile("ld.shared.v2.b32 {%0,%1},[%2];" : "=r"(v[0]), "=r"(v[1]) : "r"(a));
}
__device__ __forceinline__ void sts32(uint32_t a, uint32_t v) {
    asm volatile("st.shared.b32 [%0],%1;" :: "r"(a), "r"(v) : "memory");
}
__device__ __forceinline__ void cp16(uint32_t dst, const void* src) {
    asm volatile("cp.async.ca.shared.global [%0], [%1], 16;" :: "r"(dst), "l"(src) : "memory");
}
__device__ __forceinline__ void cp4(uint32_t dst, const void* src, uint32_t srcsz) {
    asm volatile("cp.async.ca.shared.global [%0], [%1], 4, %2;" :: "r"(dst), "l"(src), "r"(srcsz) : "memory");
}
#define CP_COMMIT() asm volatile("cp.async.commit_group;" ::: "memory")
#define CP_WAIT()   asm volatile("cp.async.wait_group 0;" ::: "memory")

__device__ __forceinline__ void mma16816(float* c, const uint32_t* a, const uint32_t* b) {
    asm volatile(
        "mma.sync.aligned.m16n8k16.row.col.f32.f16.f16.f32 "
        "{%0,%1,%2,%3}, {%4,%5,%6,%7}, {%8,%9}, {%0,%1,%2,%3};"
        : "+f"(c[0]), "+f"(c[1]), "+f"(c[2]), "+f"(c[3])
        : "r"(a[0]), "r"(a[1]), "r"(a[2]), "r"(a[3]), "r"(b[0]), "r"(b[1]));
}

// ---------------- prep: fp32 dkw -> fragment-order fp16 hi/lo ----------------
__global__ void prep_w_kernel(const float* __restrict__ dkw) {
    int idx = blockIdx.x * blockDim.x + threadIdx.x;   // uint2 granularity
    if (idx >= 4 * 96 * 2 * 24 * 4 * 32) return;       // 2359296
    int r = idx;
    int lane = r & 31; r >>= 5;
    int kt   = r & 3;  r >>= 2;
    int nt   = r % 24; r /= 24;
    int var  = r & 1;  r >>= 1;
    int i    = r % 96; r /= 96;
    int bg   = r;
    int o = nt * 8 + (lane >> 2);
    const float* wrow = dkw + (size_t)(bg * 192 + o) * 4800;
    uint32_t w2[2];
    #pragma unroll
    for (int reg = 0; reg < 2; reg++) {
        int kc = (lane & 3) * 2 + reg * 8;
        int kg = i * 64 + kt * 16 + kc;      // even
        int ch = kg >> 5, tap = kg & 31;
        float v0 = (tap < 25)     ? wrow[ch * 25 + tap]     : 0.f;
        float v1 = (tap + 1 < 25) ? wrow[ch * 25 + tap + 1] : 0.f;
        __half h0 = __float2half_rn(v0), h1 = __float2half_rn(v1);
        if (var == 0) {
            w2[reg] = pack_h2(h0, h1);
        } else {
            w2[reg] = pack_h2(__float2half_rn(v0 - __half2float(h0)),
                              __float2half_rn(v1 - __half2float(h1)));
        }
    }
    *(uint2*)&g_wF[(size_t)idx * 2] = make_uint2(w2[0], w2[1]);
}

// ---------------- main kernel ----------------
__global__ __launch_bounds__(256, 1)
void topo_mma_kernel(const float* __restrict__ xin,
                     const int*   __restrict__ topo,
                     const float* __restrict__ dkb,
                     float*       __restrict__ out)
{
    extern __shared__ char smem[];
    const uint32_t sbase = smem_u32(smem);

    const int t   = blockIdx.x;          // 0..35
    const int bg  = blockIdx.z;          // 0..3
    const int b   = bg >> 1, g = bg & 1;
    const int p0  = t * 64;
    const int r0  = p0 / 48;
    const int tid = threadIdx.x;
    const int wid = tid >> 5, lane = tid & 31;
    const int wm  = wid & 1,  wn   = wid >> 1;

    float* patchS = (float*)(smem + OFF_PATCH);
    int*   topoT  = (int*)(smem + OFF_TOPO);
    int*   maskS  = (int*)(smem + OFF_MASK);

    // ---- per-thread build constants (kp fixed per thread) ----
    const int kp   = (lane & 3) + 4 * wid;     // 0..31
    const int ktc  = kp >> 3;
    const int kb2  = (kp >> 2) & 1;
    const int chl  = kp >> 4;
    const int tap0 = (kp & 15) * 2, tap1 = tap0 + 1;
    const bool ok0 = tap0 < 25, ok1 = tap1 < 25;
    const int toff0 = (tap0 / 5) * 52 + tap0 % 5;
    const int toff1 = (tap1 / 5) * 52 + tap1 % 5;
    const int m3 = lane >> 2;

    // ---- patch cp.async slot precompute (3 slots/thread) ----
    const float* gsrc[3]; uint32_t psz[3], pdst[3];
    #pragma unroll
    for (int q = 0; q < 3; q++) {
        int idx = tid + q * 256;
        bool valid = idx < 624;
        int ch = idx / 312, rem = idx - ch * 312;
        int pr = rem / 52, cc = rem - pr * 52;
        int y = r0 - 2 + pr, x = cc - 2;
        bool inb = valid && y >= 0 && y < 48 && x >= 0 && x < 48;
        gsrc[q] = xin + (inb ? ((size_t)(b * 192 + ch) * 2304 + y * 48 + x) : 0);
        psz[q]  = inb ? 4u : 0u;
        pdst[q] = sbase + OFF_PATCH + (uint32_t)idx * 4;
    }

    // ---- stage topo patches (sentinel 127; pad never passes '<') ----
    for (int idx = tid; idx < 624; idx += 256) {
        int gi = idx / 312, rem = idx - gi * 312;
        int pr = rem / 52, cc = rem - pr * 52;
        int y = r0 - 2 + pr, x = cc - 2;
        int v = 127;
        if (y >= 0 && y < 48 && x >= 0 && x < 48)
            v = topo[(b * 2 + gi) * 2304 + y * 48 + x];
        topoT[idx] = v;
    }

    // ---- issue chunk-0 B + patch cp.async ----
    {
        const uint4* src = (const uint4*)g_wF + (size_t)(bg * 96 + 0) * 3072;
        uint32_t dstB = sbase + OFF_B + 0 * 49152 + tid * 16;
        #pragma unroll
        for (int q = 0; q < 12; q++) cp16(dstB + q * 4096, src + tid + q * 256);
        #pragma unroll
        for (int q = 0; q < 3; q++) cp4(pdst[q], gsrc[q] + 0, psz[q]);
        CP_COMMIT();
    }
    __syncthreads();    // topoT visible for mask build

    // ---- per-pixel 25-bit masks, both input groups ----
    if (tid < 128) {
        int px = tid & 63, gi = tid >> 6;
        int p = p0 + px;
        int tc = topo[(b * 2 + g) * 2304 + p];
        int py = p / 48, pxx = p - py * 48, pyl = py - r0;
        unsigned m = 0;
        #pragma unroll
        for (int kh = 0; kh < 5; kh++)
            #pragma unroll
            for (int kw = 0; kw < 5; kw++)
                if (topoT[gi * 312 + (pyl + kh) * 52 + pxx + kw] < tc)
                    m |= 1u << (kh * 5 + kw);
        maskS[tid] = (int)m;
    }
    CP_WAIT();
    __syncthreads();    // masks + patch(0) + B(0) visible

    // ---- build chunk 0 A frags ----
    {
        const int gi64 = 0;
        uint32_t Aw = sbase + OFF_A;
        #pragma unroll
        for (int s = 0; s < 8; s++) {
            int px = m3 + 8 * s;
            int p = p0 + px;
            int py = p / 48, pxx = p - py * 48, pyl = py - r0;
            unsigned mk = (unsigned)maskS[gi64 + px];
            int base = chl * 312 + pyl * 52 + pxx;
            float v0 = 0.f, v1 = 0.f;
            if (ok0 && ((mk >> tap0) & 1u)) v0 = patchS[base + toff0];
            if (ok1 && ((mk >> tap1) & 1u)) v1 = patchS[base + toff1];
            __half h0 = __float2half_rn(v0), h1 = __float2half_rn(v1);
            uint32_t a = Aw + (uint32_t)(((s >> 1) * 16 + ktc * 4 + (s & 1) + 2 * kb2) * 128) + (lane << 2);
            sts32(a, pack_h2(h0, h1));
            sts32(a + 8192, pack_h2(__float2half_rn(v0 - __half2float(h0)),
                                    __float2half_rn(v1 - __half2float(h1))));
        }
    }
    __syncthreads();    // chunk 0 built

    // ---- accumulators ----
    float acc[2][6][4];
    #pragma unroll
    for (int i0 = 0; i0 < 2; i0++)
        #pragma unroll
        for (int j = 0; j < 6; j++)
            #pragma unroll
            for (int c = 0; c < 4; c++) acc[i0][j][c] = 0.f;

    // ---- main loop: 96 chunks ----
    for (int i = 0; i < NCHUNK; i++) {
        const int bsel = i & 1;

        if (i + 1 < NCHUNK) {
            const uint4* src = (const uint4*)g_wF + (size_t)(bg * 96 + i + 1) * 3072;
            uint32_t dstB = sbase + OFF_B + (uint32_t)(bsel ^ 1) * 49152 + tid * 16;
            #pragma unroll
            for (int q = 0; q < 12; q++) cp16(dstB + q * 4096, src + tid + q * 256);
            size_t choff = (size_t)(2 * (i + 1)) * 2304;
            #pragma unroll
            for (int q = 0; q < 3; q++) cp4(pdst[q], gsrc[q] + choff, psz[q]);
            CP_COMMIT();
        }

        // ---- MMA over chunk i ----
        {
            uint32_t Ab = sbase + OFF_A + (uint32_t)bsel * 16384;
            uint32_t Bb = sbase + OFF_B + (uint32_t)bsel * 49152;
            #pragma unroll
            for (int kt = 0; kt < 4; kt++) {
                uint32_t Ah[2][4], Al[2][4], Bh[6][2], Bl[6][2];
                #pragma unroll
                for (int mtl = 0; mtl < 2; mtl++) {
                    uint32_t a = Ab + (uint32_t)(((wm * 2 + mtl) * 16 + kt * 4) * 128) + (lane << 2);
                    #pragma unroll
                    for (int r = 0; r < 4; r++) Ah[mtl][r] = lds32(a + r * 128);
                }
                #pragma unroll
                for (int ntl = 0; ntl < 6; ntl++) {
                    uint32_t a = Bb + (uint32_t)((wn * 6 + ntl) * 1024 + kt * 256) + (lane << 3);
                    lds64(Bh[ntl], a);
                }
                #pragma unroll
                for (int mtl = 0; mtl < 2; mtl++)
                    #pragma unroll
                    for (int ntl = 0; ntl < 6; ntl++)
                        mma16816(acc[mtl][ntl], Ah[mtl], Bh[ntl]);
                #pragma unroll
                for (int ntl = 0; ntl < 6; ntl++) {
                    uint32_t a = Bb + 24576u + (uint32_t)((wn * 6 + ntl) * 1024 + kt * 256) + (lane << 3);
                    lds64(Bl[ntl], a);
                }
                #pragma unroll
                for (int mtl = 0; mtl < 2; mtl++)
                    #pragma unroll
                    for (int ntl = 0; ntl < 6; ntl++)
                        mma16816(acc[mtl][ntl], Ah[mtl], Bl[ntl]);
                #pragma unroll
                for (int mtl = 0; mtl < 2; mtl++) {
                    uint32_t a = Ab + 8192u + (uint32_t)(((wm * 2 + mtl) * 16 + kt * 4) * 128) + (lane << 2);
                    #pragma unroll
                    for (int r = 0; r < 4; r++) Al[mtl][r] = lds32(a + r * 128);
                }
                #pragma unroll
                for (int mtl = 0; mtl < 2; mtl++)
                    #pragma unroll
                    for (int ntl = 0; ntl < 6; ntl++)
                        mma16816(acc[mtl][ntl], Al[mtl], Bh[ntl]);
            }
        }

        CP_WAIT();
        __syncthreads();   // cp data landed; all MMA(i) reads done

        if (i + 1 < NCHUNK) {
            // ---- build chunk i+1 A frags into buf bsel^1 ----
            const int gi64 = (i + 1 >= 48) ? 64 : 0;
            uint32_t Aw = sbase + OFF_A + (uint32_t)(bsel ^ 1) * 16384;
            #pragma unroll
            for (int s = 0; s < 8; s++) {
                int px = m3 + 8 * s;
                int p = p0 + px;
                int py = p / 48, pxx = p - py * 48, pyl = py - r0;
                unsigned mk = (unsigned)maskS[gi64 + px];
                int base = chl * 312 + pyl * 52 + pxx;
                float v0 = 0.f, v1 = 0.f;
                if (ok0 && ((mk >> tap0) & 1u)) v0 = patchS[base + toff0];
                if (ok1 && ((mk >> tap1) & 1u)) v1 = patchS[base + toff1];
                __half h0 = __float2half_rn(v0), h1 = __float2half_rn(v1);
                uint32_t a = Aw + (uint32_t)(((s >> 1) * 16 + ktc * 4 + (s & 1) + 2 * kb2) * 128) + (lane << 2);
                sts32(a, pack_h2(h0, h1));
                sts32(a + 8192, pack_h2(__float2half_rn(v0 - __half2float(h0)),
                                        __float2half_rn(v1 - __half2float(h1))));
            }
            __syncthreads();  // built chunk visible for next MMA
        }
    }

    // ---- epilogue: bias + direct store (each output written once) ----
    #pragma unroll
    for (int mtl = 0; mtl < 2; mtl++)
        #pragma unroll
        for (int ntl = 0; ntl < 6; ntl++)
            #pragma unroll
            for (int cr = 0; cr < 4; cr++) {
                int pxl = wm * 32 + mtl * 16 + (lane >> 2) + ((cr >> 1) << 3);
                int o   = wn * 48 + ntl * 8 + ((lane & 3) << 1) + (cr & 1);
                float v = acc[mtl][ntl][cr] + dkb[bg * 192 + o];
                out[(size_t)(b * 384 + g * 192 + o) * 2304 + p0 + pxl] = v;
            }
}

extern "C" void kernel_launch(void* const* d_in, const int* in_sizes, int n_in,
                              void* d_out, int out_size) {
    const float* x    = (const float*)d_in[0];   // (2,192,48,48) f32
    const int*   topo = (const int*)  d_in[1];   // (2,2,48,48)  i32
    const float* dkw  = (const float*)d_in[2];   // (2,2,192,4800,1) f32
    const float* dkb  = (const float*)d_in[3];   // (2,2,192,1) f32
    float* out = (float*)d_out;                  // (2,384,48,48) f32

    cudaFuncSetAttribute(topo_mma_kernel,
                         cudaFuncAttributeMaxDynamicSharedMemorySize, SMEM_TOTAL);

    prep_w_kernel<<<(2359296 + 255) / 256, 256>>>(dkw);

    dim3 grid(36, 1, 4);                         // 144 CTAs, one wave
    topo_mma_kernel<<<grid, 256, SMEM_TOTAL>>>(x, topo, dkb, out);
}

// round 9
// speedup vs baseline: 3.5382x; 1.0197x over previous
#include <cuda_runtime.h>
#include <cuda_fp16.h>
#include <cstdint>

// TopoGroupDynamicMaskConv2d via mma.sync m16n8k16 fp16 hi/lo (3-pass) GEMM.
// B=2, CIN=192, COUT=384, H=W=48, K=5, P=2, G=2.
// CTA tile: 64 px x 96 o, full K=6144 (192ch x 32 padded taps).
// Grid 36 x 8 (bg x o-half) = 288 CTAs -> 2 CTAs/SM, one wave.

#define NCHUNK 96            // chunks of K'=64 (2 channels x 32 padded taps)

// W fragment-ready: [z=bg*2+oh][chunk][var][nt 12][kt 4][lane 32][reg 2] b32
__device__ __align__(16) uint32_t g_wF[8u * 96u * 6144u];

// ---- dynamic smem layout (bytes) ----
#define OFF_A      0         // 2 buf x 2 var x 8192  = 32768
#define OFF_B      32768     // 2 buf x 2 var x 12288 = 49152
#define OFF_PATCH  81920     // 768 f32 (624 used; padding absorbs cp4 zero-fills)
#define OFF_TOPO   84992     // 624 ints (2 gi x 6 x 52)
#define OFF_MASK   87488     // 128 ints (2 gi x 64 px)
#define SMEM_TOTAL 88000

__device__ __forceinline__ uint32_t smem_u32(const void* p) {
    uint32_t a;
    asm("{ .reg .u64 t; cvta.to.shared.u64 t, %1; cvt.u32.u64 %0, t; }" : "=r"(a) : "l"(p));
    return a;
}
__device__ __forceinline__ uint32_t pack_h2(__half lo, __half hi) {
    return ((uint32_t)__half_as_ushort(hi) << 16) | (uint32_t)__half_as_ushort(lo);
}
__device__ __forceinline__ void lds64(uint32_t* v, uint32_t a) {
    asm volatile("ld.shared.v2.b32 {%0,%1},[%2];" : "=r"(v[0]), "=r"(v[1]) : "r"(a));
}
__device__ __forceinline__ void sts32(uint32_t a, uint32_t v) {
    asm volatile("st.shared.b32 [%0],%1;" :: "r"(a), "r"(v) : "memory");
}
__device__ __forceinline__ void cp16(uint32_t dst, const void* src) {
    asm volatile("cp.async.ca.shared.global [%0], [%1], 16;" :: "r"(dst), "l"(src) : "memory");
}
__device__ __forceinline__ void cp4(uint32_t dst, const void* src, uint32_t srcsz) {
    asm volatile("cp.async.ca.shared.global [%0], [%1], 4, %2;" :: "r"(dst), "l"(src), "r"(srcsz) : "memory");
}
#define CP_COMMIT() asm volatile("cp.async.commit_group;" ::: "memory")
#define CP_WAIT()   asm volatile("cp.async.wait_group 0;" ::: "memory")

__device__ __forceinline__ void mma16816(float* c, const uint32_t* a, const uint32_t* b) {
    asm volatile(
        "mma.sync.aligned.m16n8k16.row.col.f32.f16.f16.f32 "
        "{%0,%1,%2,%3}, {%4,%5,%6,%7}, {%8,%9}, {%0,%1,%2,%3};"
        : "+f"(c[0]), "+f"(c[1]), "+f"(c[2]), "+f"(c[3])
        : "r"(a[0]), "r"(a[1]), "r"(a[2]), "r"(a[3]), "r"(b[0]), "r"(b[1]));
}

// ---------------- prep: fp32 dkw -> fragment-order fp16 hi/lo ----------------
__global__ void prep_w_kernel(const float* __restrict__ dkw) {
    int idx = blockIdx.x * blockDim.x + threadIdx.x;   // uint2 granularity
    if (idx >= 8 * 96 * 2 * 12 * 4 * 32) return;       // 2359296
    int r = idx;
    int lane = r & 31; r >>= 5;
    int kt   = r & 3;  r >>= 2;
    int nt   = r % 12; r /= 12;
    int var  = r & 1;  r >>= 1;
    int i    = r % 96; r /= 96;
    int z    = r;                       // bg*2 + oh
    int bg = z >> 1, oh = z & 1;
    int o = oh * 96 + nt * 8 + (lane >> 2);
    const float* wrow = dkw + (size_t)(bg * 192 + o) * 4800;
    uint32_t w2[2];
    #pragma unroll
    for (int reg = 0; reg < 2; reg++) {
        int kc = (lane & 3) * 2 + reg * 8;
        int kg = i * 64 + kt * 16 + kc;      // even
        int ch = kg >> 5, tap = kg & 31;
        float v0 = (tap < 25)     ? wrow[ch * 25 + tap]     : 0.f;
        float v1 = (tap + 1 < 25) ? wrow[ch * 25 + tap + 1] : 0.f;
        __half h0 = __float2half_rn(v0), h1 = __float2half_rn(v1);
        if (var == 0) {
            w2[reg] = pack_h2(h0, h1);
        } else {
            w2[reg] = pack_h2(__float2half_rn(v0 - __half2float(h0)),
                              __float2half_rn(v1 - __half2float(h1)));
        }
    }
    *(uint2*)&g_wF[(size_t)idx * 2] = make_uint2(w2[0], w2[1]);
}

// ---------------- main kernel ----------------
__global__ __launch_bounds__(256, 2)
void topo_mma_kernel(const float* __restrict__ xin,
                     const int*   __restrict__ topo,
                     const float* __restrict__ dkb,
                     float*       __restrict__ out)
{
    extern __shared__ char smem[];
    const uint32_t sbase = smem_u32(smem);

    const int t   = blockIdx.x;          // 0..35 px tile (64 px)
    const int z   = blockIdx.z;          // 0..7: bg*2 + oh
    const int bg  = z >> 1, oh = z & 1;
    const int b   = bg >> 1, g = bg & 1;
    const int p0  = t * 64;
    const int r0  = p0 / 48;
    const int tid = threadIdx.x;
    const int wid = tid >> 5, lane = tid & 31;
    const int wm  = wid & 1,  wn   = wid >> 1;       // wn 0..3 (24 o each)

    float* patchS = (float*)(smem + OFF_PATCH);
    int*   topoT  = (int*)(smem + OFF_TOPO);
    int*   maskS  = (int*)(smem + OFF_MASK);

    // ---- per-thread A-build constants (kp fixed per thread) ----
    const int kp   = (lane & 3) + 4 * wid;     // 0..31 (k pair)
    const int ktc  = kp >> 3;                  // k16 block
    const int kb2  = (kp >> 2) & 1;            // k-high half (regs 2,3)
    const int chl  = kp >> 4;                  // channel within chunk
    const int tap0 = (kp & 15) * 2, tap1 = tap0 + 1;
    const bool ok0 = tap0 < 25, ok1 = tap1 < 25;
    const int toff0 = (tap0 / 5) * 52 + tap0 % 5;
    const int toff1 = (tap1 / 5) * 52 + tap1 % 5;
    const int m3 = lane >> 2;

    // ---- patch cp.async slot precompute (3 slots/thread) ----
    // Slots 624..767 are inactive: cp.async with src-size 0 still zero-fills
    // the 4 dst bytes, so they MUST land inside the padded patch region.
    const float* gsrc[3]; uint32_t psz[3], pdst[3];
    #pragma unroll
    for (int q = 0; q < 3; q++) {
        int idx = tid + q * 256;
        bool valid = idx < 624;
        int ch = idx / 312, rem = idx - ch * 312;
        int pr = rem / 52, cc = rem - pr * 52;
        int y = r0 - 2 + pr, x = cc - 2;
        bool inb = valid && y >= 0 && y < 48 && x >= 0 && x < 48;
        gsrc[q] = xin + (inb ? ((size_t)(b * 192 + ch) * 2304 + y * 48 + x) : 0);
        psz[q]  = inb ? 4u : 0u;
        pdst[q] = sbase + OFF_PATCH + (uint32_t)idx * 4;   // idx<768 stays in patch pad
    }

    // ---- stage topo patches (sentinel 127; pad never passes '<') ----
    for (int idx = tid; idx < 624; idx += 256) {
        int gi = idx / 312, rem = idx - gi * 312;
        int pr = rem / 52, cc = rem - pr * 52;
        int y = r0 - 2 + pr, x = cc - 2;
        int v = 127;
        if (y >= 0 && y < 48 && x >= 0 && x < 48)
            v = topo[(b * 2 + gi) * 2304 + y * 48 + x];
        topoT[idx] = v;
    }

    // ---- issue chunk-0 B + patch cp.async ----
    {
        const uint4* src = (const uint4*)g_wF + (size_t)(z * 96 + 0) * 1536;
        uint32_t dstB = sbase + OFF_B + tid * 16;
        #pragma unroll
        for (int q = 0; q < 6; q++) cp16(dstB + q * 4096, src + tid + q * 256);
        #pragma unroll
        for (int q = 0; q < 3; q++) cp4(pdst[q], gsrc[q] + 0, psz[q]);
        CP_COMMIT();
    }
    __syncthreads();    // topoT visible

    // ---- per-pixel 25-bit masks, both input groups ----
    if (tid < 128) {
        int px = tid & 63, gi = tid >> 6;
        int p = p0 + px;
        int tc = topo[(b * 2 + g) * 2304 + p];
        int py = p / 48, pxx = p - py * 48, pyl = py - r0;
        unsigned m = 0;
        #pragma unroll
        for (int kh = 0; kh < 5; kh++)
            #pragma unroll
            for (int kw = 0; kw < 5; kw++)
                if (topoT[gi * 312 + (pyl + kh) * 52 + pxx + kw] < tc)
                    m |= 1u << (kh * 5 + kw);
        maskS[tid] = (int)m;
    }
    CP_WAIT();
    __syncthreads();    // masks + patch(0) + B(0) visible

    // ---- build chunk 0 A frags (buf 0) ----
    {
        uint32_t Aw = sbase + OFF_A;
        #pragma unroll
        for (int s = 0; s < 8; s++) {
            int px = m3 + 8 * s;
            int p = p0 + px;
            int py = p / 48, pxx = p - py * 48, pyl = py - r0;
            unsigned mk = (unsigned)maskS[px];           // gi=0 for chunk 0
            int base = chl * 312 + pyl * 52 + pxx;
            float v0 = 0.f, v1 = 0.f;
            if (ok0 && ((mk >> tap0) & 1u)) v0 = patchS[base + toff0];
            if (ok1 && ((mk >> tap1) & 1u)) v1 = patchS[base + toff1];
            __half h0 = __float2half_rn(v0), h1 = __float2half_rn(v1);
            uint32_t a = Aw + (uint32_t)((((s >> 1) * 4 + ktc) * 512) + kb2 * 256 + (s & 1) * 4)
                            + (uint32_t)(lane << 3);
            sts32(a, pack_h2(h0, h1));
            sts32(a + 8192, pack_h2(__float2half_rn(v0 - __half2float(h0)),
                                    __float2half_rn(v1 - __half2float(h1))));
        }
    }
    __syncthreads();    // chunk 0 built

    // ---- accumulators: 2 mt x 3 nt x 4 ----
    float acc[2][3][4];
    #pragma unroll
    for (int i0 = 0; i0 < 2; i0++)
        #pragma unroll
        for (int j = 0; j < 3; j++)
            #pragma unroll
            for (int c = 0; c < 4; c++) acc[i0][j][c] = 0.f;

    // ---- main loop: 96 chunks ----
    for (int i = 0; i < NCHUNK; i++) {
        const int bsel = i & 1;

        if (i + 1 < NCHUNK) {
            const uint4* src = (const uint4*)g_wF + (size_t)(z * 96 + i + 1) * 1536;
            uint32_t dstB = sbase + OFF_B + (uint32_t)(bsel ^ 1) * 24576 + tid * 16;
            #pragma unroll
            for (int q = 0; q < 6; q++) cp16(dstB + q * 4096, src + tid + q * 256);
            size_t choff = (size_t)(2 * (i + 1)) * 2304;
            #pragma unroll
            for (int q = 0; q < 3; q++) cp4(pdst[q], gsrc[q] + choff, psz[q]);
            CP_COMMIT();
        }

        // ---- MMA over chunk i ----
        {
            uint32_t Ab = sbase + OFF_A + (uint32_t)bsel * 16384;
            uint32_t Bb = sbase + OFF_B + (uint32_t)bsel * 24576;
            #pragma unroll
            for (int kt = 0; kt < 4; kt++) {
                uint32_t Ah[2][4], Al[2][4], Bh[3][2], Bl[3][2];
                #pragma unroll
                for (int mtl = 0; mtl < 2; mtl++) {
                    uint32_t a = Ab + (uint32_t)((((wm * 2 + mtl) * 4 + kt) * 512)) + (lane << 3);
                    lds64(&Ah[mtl][0], a);
                    lds64(&Ah[mtl][2], a + 256);
                }
                #pragma unroll
                for (int ntl = 0; ntl < 3; ntl++)
                    lds64(Bh[ntl], Bb + (uint32_t)((wn * 3 + ntl) * 1024 + kt * 256) + (lane << 3));
                #pragma unroll
                for (int mtl = 0; mtl < 2; mtl++)
                    #pragma unroll
                    for (int ntl = 0; ntl < 3; ntl++)
                        mma16816(acc[mtl][ntl], Ah[mtl], Bh[ntl]);
                #pragma unroll
                for (int ntl = 0; ntl < 3; ntl++)
                    lds64(Bl[ntl], Bb + 12288u + (uint32_t)((wn * 3 + ntl) * 1024 + kt * 256) + (lane << 3));
                #pragma unroll
                for (int mtl = 0; mtl < 2; mtl++)
                    #pragma unroll
                    for (int ntl = 0; ntl < 3; ntl++)
                        mma16816(acc[mtl][ntl], Ah[mtl], Bl[ntl]);
                #pragma unroll
                for (int mtl = 0; mtl < 2; mtl++) {
                    uint32_t a = Ab + 8192u + (uint32_t)((((wm * 2 + mtl) * 4 + kt) * 512)) + (lane << 3);
                    lds64(&Al[mtl][0], a);
                    lds64(&Al[mtl][2], a + 256);
                }
                #pragma unroll
                for (int mtl = 0; mtl < 2; mtl++)
                    #pragma unroll
                    for (int ntl = 0; ntl < 3; ntl++)
                        mma16816(acc[mtl][ntl], Al[mtl], Bh[ntl]);
            }
        }

        CP_WAIT();
        __syncthreads();   // cp data landed; all MMA(i) reads done

        if (i + 1 < NCHUNK) {
            // ---- build chunk i+1 A frags into buf bsel^1 ----
            const int gi64 = (i + 1 >= 48) ? 64 : 0;
            uint32_t Aw = sbase + OFF_A + (uint32_t)(bsel ^ 1) * 16384;
            #pragma unroll
            for (int s = 0; s < 8; s++) {
                int px = m3 + 8 * s;
                int p = p0 + px;
                int py = p / 48, pxx = p - py * 48, pyl = py - r0;
                unsigned mk = (unsigned)maskS[gi64 + px];
                int base = chl * 312 + pyl * 52 + pxx;
                float v0 = 0.f, v1 = 0.f;
                if (ok0 && ((mk >> tap0) & 1u)) v0 = patchS[base + toff0];
                if (ok1 && ((mk >> tap1) & 1u)) v1 = patchS[base + toff1];
                __half h0 = __float2half_rn(v0), h1 = __float2half_rn(v1);
                uint32_t a = Aw + (uint32_t)((((s >> 1) * 4 + ktc) * 512) + kb2 * 256 + (s & 1) * 4)
                                + (uint32_t)(lane << 3);
                sts32(a, pack_h2(h0, h1));
                sts32(a + 8192, pack_h2(__float2half_rn(v0 - __half2float(h0)),
                                        __float2half_rn(v1 - __half2float(h1))));
            }
            __syncthreads();  // built chunk visible for next MMA
        }
    }

    // ---- epilogue: bias + direct store ----
    #pragma unroll
    for (int mtl = 0; mtl < 2; mtl++)
        #pragma unroll
        for (int ntl = 0; ntl < 3; ntl++)
            #pragma unroll
            for (int cr = 0; cr < 4; cr++) {
                int pxl = wm * 32 + mtl * 16 + (lane >> 2) + ((cr >> 1) << 3);
                int o   = oh * 96 + wn * 24 + ntl * 8 + ((lane & 3) << 1) + (cr & 1);
                float v = acc[mtl][ntl][cr] + dkb[bg * 192 + o];
                out[(size_t)(b * 384 + g * 192 + o) * 2304 + p0 + pxl] = v;
            }
}

extern "C" void kernel_launch(void* const* d_in, const int* in_sizes, int n_in,
                              void* d_out, int out_size) {
    const float* x    = (const float*)d_in[0];   // (2,192,48,48) f32
    const int*   topo = (const int*)  d_in[1];   // (2,2,48,48)  i32
    const float* dkw  = (const float*)d_in[2];   // (2,2,192,4800,1) f32
    const float* dkb  = (const float*)d_in[3];   // (2,2,192,1) f32
    float* out = (float*)d_out;                  // (2,384,48,48) f32

    cudaFuncSetAttribute(topo_mma_kernel,
                         cudaFuncAttributeMaxDynamicSharedMemorySize, SMEM_TOTAL);

    prep_w_kernel<<<(2359296 + 255) / 256, 256>>>(dkw);

    dim3 grid(36, 1, 8);                         // 288 CTAs -> 2/SM, one wave
    topo_mma_kernel<<<grid, 256, SMEM_TOTAL>>>(x, topo, dkb, out);
}